// round 1
// baseline (speedup 1.0000x reference)
#include <cuda_runtime.h>
#include <math.h>

// Problem constants
#define B_   4
#define L_   2048
#define DIM_ 1024
#define DFF_ 4096
#define NTOK (B_ * L_)            // 8192 rows
#define CS   64                    // conv chunk size
#define NC   (L_ / CS)             // 32 chunks

// -------- scratch (static __device__ — no allocations allowed) --------
__device__ float  g_hln[(size_t)NTOK * DIM_];   // LN1 output        (32 MB)
__device__ float  g_y  [(size_t)NTOK * DIM_];   // conv + residual   (32 MB)
__device__ float  g_h2 [(size_t)NTOK * DIM_];   // LN2 output        (32 MB)
__device__ float  g_act[(size_t)NTOK * DFF_];   // SiLU(h2@w1+b1)    (128 MB)
__device__ float2 g_carry[B_ * NC * DIM_];
__device__ float2 g_zin  [B_ * NC * DIM_];
__device__ float2 g_p    [DIM_];
__device__ float2 g_pinit[DIM_];
__device__ float2 g_p64  [DIM_];

// ---------------- phazor precompute ----------------
__global__ void phazor_prep(const float* __restrict__ phazor,
                            const float* __restrict__ phazor_init) {
    int d = blockIdx.x * blockDim.x + threadIdx.x;
    if (d >= DIM_) return;
    float pr = phazor[2 * d], pim = phazor[2 * d + 1];
    float pa = sqrtf(pr * pr + pim * pim);
    float s = expf(-pa) / pa;                 // p/|p| * exp(-|p|)
    float2 p = make_float2(pr * s, pim * s);
    g_p[d] = p;
    g_pinit[d] = make_float2(phazor_init[2 * d], phazor_init[2 * d + 1]);
    float2 q = p;                              // p^64 via 6 squarings
    #pragma unroll
    for (int i = 0; i < 6; i++) {
        float nr = q.x * q.x - q.y * q.y;
        q.y = 2.f * q.x * q.y;
        q.x = nr;
    }
    g_p64[d] = q;
}

// ---------------- layernorm (one block per token row) ----------------
__global__ void ln_kernel(const float* __restrict__ x, const float* __restrict__ g,
                          const float* __restrict__ bb, float* __restrict__ out) {
    int row = blockIdx.x;                      // 0..8191
    int tid = threadIdx.x;                     // 256 threads, 4 elems each
    const float4* xr = (const float4*)(x + (size_t)row * DIM_);
    float4 v = xr[tid];
    float s  = v.x + v.y + v.z + v.w;
    float ss = v.x * v.x + v.y * v.y + v.z * v.z + v.w * v.w;
    #pragma unroll
    for (int o = 16; o > 0; o >>= 1) {
        s  += __shfl_xor_sync(0xffffffffu, s, o);
        ss += __shfl_xor_sync(0xffffffffu, ss, o);
    }
    __shared__ float sh[16];
    int w = tid >> 5;
    if ((tid & 31) == 0) { sh[w] = s; sh[w + 8] = ss; }
    __syncthreads();
    if (tid < 32) {
        float a = (tid < 8) ? sh[tid] : 0.f;
        float c = (tid < 8) ? sh[tid + 8] : 0.f;
        #pragma unroll
        for (int o = 4; o > 0; o >>= 1) {
            a += __shfl_xor_sync(0xffffffffu, a, o);
            c += __shfl_xor_sync(0xffffffffu, c, o);
        }
        if (tid == 0) { sh[0] = a; sh[1] = c; }
    }
    __syncthreads();
    float mu  = sh[0] * (1.f / DIM_);
    float var = sh[1] * (1.f / DIM_) - mu * mu;
    float inv = rsqrtf(var + 1e-5f);
    float4 gv = ((const float4*)g)[tid];
    float4 bv = ((const float4*)bb)[tid];
    float4 o4;
    o4.x = (v.x - mu) * inv * gv.x + bv.x;
    o4.y = (v.y - mu) * inv * gv.y + bv.y;
    o4.z = (v.z - mu) * inv * gv.z + bv.z;
    o4.w = (v.w - mu) * inv * gv.w + bv.w;
    ((float4*)(out + (size_t)row * DIM_))[tid] = o4;
}

// ---------------- spiral conv: 3-phase chunked scan ----------------
// phase 1: per-(b,chunk,d) local carry  z_c = sum_{j} p^{CS-1-j} h[j]
__global__ void conv_phase1(const float* __restrict__ h) {
    int b = blockIdx.x >> 5, c = blockIdx.x & 31, d = threadIdx.x;
    float2 p = g_p[d];
    float zr = 0.f, zi = 0.f;
    const float* hp = h + ((size_t)b * L_ + c * CS) * DIM_ + d;
    #pragma unroll 4
    for (int j = 0; j < CS; j++) {
        float hv = hp[(size_t)j * DIM_];
        float nr = p.x * zr - p.y * zi + hv;
        zi = p.x * zi + p.y * zr;
        zr = nr;
    }
    g_carry[(b * NC + c) * DIM_ + d] = make_float2(zr, zi);
}

// phase 2: exclusive prefix of carries across chunks (p^64 combine)
__global__ void conv_phase2() {
    int b = blockIdx.x, d = threadIdx.x;
    float2 pc = g_p64[d];
    float zr = 0.f, zi = 0.f;
    #pragma unroll
    for (int c = 0; c < NC; c++) {
        int idx = (b * NC + c) * DIM_ + d;
        g_zin[idx] = make_float2(zr, zi);
        float2 cv = g_carry[idx];
        float nr = pc.x * zr - pc.y * zi + cv.x;
        zi = pc.x * zi + pc.y * zr + cv.y;
        zr = nr;
    }
}

// phase 3: re-scan chunk with true initial state, emit y = conv + past + x
__global__ void conv_phase3(const float* __restrict__ h, const float* __restrict__ x,
                            const float* __restrict__ lre, const float* __restrict__ lim,
                            float* __restrict__ y) {
    int b = blockIdx.x >> 5, c = blockIdx.x & 31, d = threadIdx.x;
    float2 p  = g_p[d];
    float2 pi = g_pinit[d];
    float2 pc = g_p64[d];
    float2 z  = g_zin[(b * NC + c) * DIM_ + d];
    // pw = p^(c*CS + 1)
    float twr = 1.f, twi = 0.f;
    for (int i = 0; i < c; i++) {
        float nr = twr * pc.x - twi * pc.y;
        twi = twr * pc.y + twi * pc.x;
        twr = nr;
    }
    float pwr = twr * p.x - twi * p.y;
    float pwi = twr * p.y + twi * p.x;
    float lr = lre[b * DIM_ + d], li = lim[b * DIM_ + d];
    size_t base = ((size_t)b * L_ + c * CS) * DIM_ + d;
    #pragma unroll 4
    for (int j = 0; j < CS; j++) {
        float hv = h[base + (size_t)j * DIM_];
        float nr = p.x * z.x - p.y * z.y + hv;
        z.y = p.x * z.y + p.y * z.x;
        z.x = nr;
        float val = pi.x * z.x - pi.y * z.y + lr * pwr - li * pwi;
        y[base + (size_t)j * DIM_] = val + x[base + (size_t)j * DIM_];
        float npr = pwr * p.x - pwi * p.y;
        pwi = pwr * p.y + pwi * p.x;
        pwr = npr;
    }
}

// ---------------- fp32 tiled SGEMM, fused epilogues ----------------
// EPI==0: out = silu(acc + bias)     (GEMM1)
// EPI==1: out = acc + bias + res     (GEMM2)
template <int EPI>
__global__ __launch_bounds__(256, 2) void sgemm_kernel(
    const float* __restrict__ A, const float* __restrict__ Bm,
    const float* __restrict__ bias, const float* __restrict__ res,
    float* __restrict__ C, int M, int N, int K) {
    const int BM = 128, BN = 128, BK = 8;
    __shared__ float As[BK][BM];
    __shared__ float Bs[BK][BN];
    int bm = blockIdx.y * BM, bn = blockIdx.x * BN;
    int tid = threadIdx.x;
    int arow = tid >> 1, acol = (tid & 1) * 4;          // A tile 128x8, float4
    int brow = tid >> 5, bcol = (tid & 31) * 4;         // B tile 8x128, float4
    int tm0 = (tid >> 4) * 8;
    int tn0 = (tid & 15) * 8;
    float acc[8][8];
    #pragma unroll
    for (int i = 0; i < 8; i++)
        #pragma unroll
        for (int j = 0; j < 8; j++) acc[i][j] = 0.f;

    for (int k0 = 0; k0 < K; k0 += BK) {
        float4 av = *(const float4*)&A[(size_t)(bm + arow) * K + k0 + acol];
        As[acol + 0][arow] = av.x;
        As[acol + 1][arow] = av.y;
        As[acol + 2][arow] = av.z;
        As[acol + 3][arow] = av.w;
        float4 bv = *(const float4*)&Bm[(size_t)(k0 + brow) * N + bn + bcol];
        *(float4*)&Bs[brow][bcol] = bv;
        __syncthreads();
        #pragma unroll
        for (int k = 0; k < BK; k++) {
            float ra[8], rb[8];
            *(float4*)(ra)     = *(float4*)&As[k][tm0];
            *(float4*)(ra + 4) = *(float4*)&As[k][tm0 + 4];
            *(float4*)(rb)     = *(float4*)&Bs[k][tn0];
            *(float4*)(rb + 4) = *(float4*)&Bs[k][tn0 + 4];
            #pragma unroll
            for (int i = 0; i < 8; i++)
                #pragma unroll
                for (int j = 0; j < 8; j++) acc[i][j] += ra[i] * rb[j];
        }
        __syncthreads();
    }

    #pragma unroll
    for (int i = 0; i < 8; i++) {
        size_t rowoff = (size_t)(bm + tm0 + i) * N + bn + tn0;
        float4 o0, o1;
        float* po = (float*)&o0;
        #pragma unroll
        for (int j = 0; j < 8; j++) {
            float v = acc[i][j] + bias[bn + tn0 + j];
            if (EPI == 0) {
                v = v / (1.f + expf(-v));                 // SiLU
            } else {
                v += res[rowoff + j];                      // bias + residual
            }
            if (j < 4) ((float*)&o0)[j] = v; else ((float*)&o1)[j - 4] = v;
        }
        (void)po;
        *(float4*)&C[rowoff]     = o0;
        *(float4*)&C[rowoff + 4] = o1;
    }
}

// ---------------- launch ----------------
extern "C" void kernel_launch(void* const* d_in, const int* in_sizes, int n_in,
                              void* d_out, int out_size) {
    const float* x      = (const float*)d_in[0];
    const float* ln_g   = (const float*)d_in[1];
    const float* ln_b   = (const float*)d_in[2];
    const float* phazor = (const float*)d_in[3];
    const float* phinit = (const float*)d_in[4];
    const float* w1     = (const float*)d_in[5];
    const float* b1     = (const float*)d_in[6];
    const float* w2     = (const float*)d_in[7];
    const float* b2     = (const float*)d_in[8];
    const float* lre    = (const float*)d_in[9];
    const float* lim    = (const float*)d_in[10];
    float* out = (float*)d_out;

    float *hln, *y, *h2, *act;
    cudaGetSymbolAddress((void**)&hln, g_hln);
    cudaGetSymbolAddress((void**)&y,   g_y);
    cudaGetSymbolAddress((void**)&h2,  g_h2);
    cudaGetSymbolAddress((void**)&act, g_act);

    phazor_prep<<<1, DIM_>>>(phazor, phinit);
    ln_kernel<<<NTOK, 256>>>(x, ln_g, ln_b, hln);
    conv_phase1<<<B_ * NC, DIM_>>>(hln);
    conv_phase2<<<B_, DIM_>>>();
    conv_phase3<<<B_ * NC, DIM_>>>(hln, x, lre, lim, y);
    ln_kernel<<<NTOK, 256>>>(y, ln_g, ln_b, h2);

    dim3 g1(DFF_ / 128, NTOK / 128);
    sgemm_kernel<0><<<g1, 256>>>(h2, w1, b1, nullptr, act, NTOK, DFF_, DIM_);
    dim3 g2(DIM_ / 128, NTOK / 128);
    sgemm_kernel<1><<<g2, 256>>>(act, w2, b2, y, out, NTOK, DIM_, DFF_);
}

// round 2
// speedup vs baseline: 2.4518x; 2.4518x over previous
#include <cuda_runtime.h>
#include <math.h>
#include <stdint.h>

// Problem constants
#define B_   4
#define L_   2048
#define DIM_ 1024
#define DFF_ 4096
#define NTOK (B_ * L_)            // 8192 rows
#define CS   64                    // conv chunk size
#define NC   (L_ / CS)             // 32 chunks

// -------- scratch (static __device__ — no allocations allowed) --------
__device__ float  g_hln[(size_t)NTOK * DIM_];
__device__ float  g_y  [(size_t)NTOK * DIM_];
__device__ float  g_h2 [(size_t)NTOK * DIM_];
__device__ float  g_act[(size_t)NTOK * DFF_];
__device__ float2 g_carry[B_ * NC * DIM_];
__device__ float2 g_zin  [B_ * NC * DIM_];
__device__ float2 g_p    [DIM_];
__device__ float2 g_pinit[DIM_];
__device__ float2 g_p64  [DIM_];

// ---------------- phazor precompute ----------------
__global__ void phazor_prep(const float* __restrict__ phazor,
                            const float* __restrict__ phazor_init) {
    int d = blockIdx.x * blockDim.x + threadIdx.x;
    if (d >= DIM_) return;
    float pr = phazor[2 * d], pim = phazor[2 * d + 1];
    float pa = sqrtf(pr * pr + pim * pim);
    float s = expf(-pa) / pa;
    float2 p = make_float2(pr * s, pim * s);
    g_p[d] = p;
    g_pinit[d] = make_float2(phazor_init[2 * d], phazor_init[2 * d + 1]);
    float2 q = p;
    #pragma unroll
    for (int i = 0; i < 6; i++) {
        float nr = q.x * q.x - q.y * q.y;
        q.y = 2.f * q.x * q.y;
        q.x = nr;
    }
    g_p64[d] = q;
}

// ---------------- layernorm ----------------
__global__ void ln_kernel(const float* __restrict__ x, const float* __restrict__ g,
                          const float* __restrict__ bb, float* __restrict__ out) {
    int row = blockIdx.x;
    int tid = threadIdx.x;
    const float4* xr = (const float4*)(x + (size_t)row * DIM_);
    float4 v = xr[tid];
    float s  = v.x + v.y + v.z + v.w;
    float ss = v.x * v.x + v.y * v.y + v.z * v.z + v.w * v.w;
    #pragma unroll
    for (int o = 16; o > 0; o >>= 1) {
        s  += __shfl_xor_sync(0xffffffffu, s, o);
        ss += __shfl_xor_sync(0xffffffffu, ss, o);
    }
    __shared__ float sh[16];
    int w = tid >> 5;
    if ((tid & 31) == 0) { sh[w] = s; sh[w + 8] = ss; }
    __syncthreads();
    if (tid < 32) {
        float a = (tid < 8) ? sh[tid] : 0.f;
        float c = (tid < 8) ? sh[tid + 8] : 0.f;
        #pragma unroll
        for (int o = 4; o > 0; o >>= 1) {
            a += __shfl_xor_sync(0xffffffffu, a, o);
            c += __shfl_xor_sync(0xffffffffu, c, o);
        }
        if (tid == 0) { sh[0] = a; sh[1] = c; }
    }
    __syncthreads();
    float mu  = sh[0] * (1.f / DIM_);
    float var = sh[1] * (1.f / DIM_) - mu * mu;
    float inv = rsqrtf(var + 1e-5f);
    float4 gv = ((const float4*)g)[tid];
    float4 bv = ((const float4*)bb)[tid];
    float4 o4;
    o4.x = (v.x - mu) * inv * gv.x + bv.x;
    o4.y = (v.y - mu) * inv * gv.y + bv.y;
    o4.z = (v.z - mu) * inv * gv.z + bv.z;
    o4.w = (v.w - mu) * inv * gv.w + bv.w;
    ((float4*)(out + (size_t)row * DIM_))[tid] = o4;
}

// ---------------- spiral conv: 3-phase chunked scan ----------------
__global__ void conv_phase1(const float* __restrict__ h) {
    int b = blockIdx.x >> 5, c = blockIdx.x & 31, d = threadIdx.x;
    float2 p = g_p[d];
    float zr = 0.f, zi = 0.f;
    const float* hp = h + ((size_t)b * L_ + c * CS) * DIM_ + d;
    #pragma unroll 4
    for (int j = 0; j < CS; j++) {
        float hv = hp[(size_t)j * DIM_];
        float nr = p.x * zr - p.y * zi + hv;
        zi = p.x * zi + p.y * zr;
        zr = nr;
    }
    g_carry[(b * NC + c) * DIM_ + d] = make_float2(zr, zi);
}

__global__ void conv_phase2() {
    int b = blockIdx.x, d = threadIdx.x;
    float2 pc = g_p64[d];
    float zr = 0.f, zi = 0.f;
    #pragma unroll
    for (int c = 0; c < NC; c++) {
        int idx = (b * NC + c) * DIM_ + d;
        g_zin[idx] = make_float2(zr, zi);
        float2 cv = g_carry[idx];
        float nr = pc.x * zr - pc.y * zi + cv.x;
        zi = pc.x * zi + pc.y * zr + cv.y;
        zr = nr;
    }
}

__global__ void conv_phase3(const float* __restrict__ h, const float* __restrict__ x,
                            const float* __restrict__ lre, const float* __restrict__ lim,
                            float* __restrict__ y) {
    int b = blockIdx.x >> 5, c = blockIdx.x & 31, d = threadIdx.x;
    float2 p  = g_p[d];
    float2 pi = g_pinit[d];
    float2 pc = g_p64[d];
    float2 z  = g_zin[(b * NC + c) * DIM_ + d];
    float twr = 1.f, twi = 0.f;
    for (int i = 0; i < c; i++) {
        float nr = twr * pc.x - twi * pc.y;
        twi = twr * pc.y + twi * pc.x;
        twr = nr;
    }
    float pwr = twr * p.x - twi * p.y;
    float pwi = twr * p.y + twi * p.x;
    float lr = lre[b * DIM_ + d], li = lim[b * DIM_ + d];
    size_t base = ((size_t)b * L_ + c * CS) * DIM_ + d;
    #pragma unroll 4
    for (int j = 0; j < CS; j++) {
        float hv = h[base + (size_t)j * DIM_];
        float nr = p.x * z.x - p.y * z.y + hv;
        z.y = p.x * z.y + p.y * z.x;
        z.x = nr;
        float val = pi.x * z.x - pi.y * z.y + lr * pwr - li * pwi;
        y[base + (size_t)j * DIM_] = val + x[base + (size_t)j * DIM_];
        float npr = pwr * p.x - pwi * p.y;
        pwi = pwr * p.y + pwi * p.x;
        pwr = npr;
    }
}

// ---------------- tf32 tensor-core GEMM (mma.sync m16n8k8) ----------------
// Block tile 128x128, BK=16, 4 warps each 64x64. Double-buffered cp.async.
// EPI==0: out = silu(acc + bias);  EPI==1: out = acc + bias + res
#define BM 128
#define BN 128
#define BK 16
#define AS_STRIDE 20    // 16 + 4 pad  (20 mod 32 -> conflict-free frags)
#define BS_STRIDE 136   // 128 + 8 pad (8 mod 32 -> conflict-free frags)

__device__ __forceinline__ uint32_t cvt_tf32(float v) {
    uint32_t r;
    asm volatile("cvt.rna.tf32.f32 %0, %1;" : "=r"(r) : "f"(v));
    return r;
}
__device__ __forceinline__ void cp_async16(uint32_t saddr, const void* gptr) {
    asm volatile("cp.async.cg.shared.global [%0], [%1], 16;" :: "r"(saddr), "l"(gptr));
}
__device__ __forceinline__ uint32_t smem_u32(const void* p) {
    return (uint32_t)__cvta_generic_to_shared(p);
}

template <int EPI>
__global__ __launch_bounds__(128, 2) void tc_gemm(
    const float* __restrict__ A, const float* __restrict__ Bm,
    const float* __restrict__ bias, const float* __restrict__ res,
    float* __restrict__ C, int M, int N, int K) {
    __shared__ float As[2][BM * AS_STRIDE];
    __shared__ float Bs[2][BK * BS_STRIDE];

    int tid = threadIdx.x;
    int wid = tid >> 5, lane = tid & 31;
    int g = lane >> 2, l4 = lane & 3;
    int wm = (wid & 1) * 64;          // warp row offset
    int wn = (wid >> 1) * 64;         // warp col offset
    int bm = blockIdx.y * BM, bn = blockIdx.x * BN;

    // global load assignments
    // A: row = tid, 4 x float4 along k
    const float* ga = A + (size_t)(bm + tid) * K;
    // B: row = tid>>3 (0..15), col4 = (tid&7) + 8*j
    int brow = tid >> 3, bc0 = tid & 7;
    const float* gb = Bm + (size_t)brow * N + bn;

    float acc[4][8][4];
    #pragma unroll
    for (int i = 0; i < 4; i++)
        #pragma unroll
        for (int j = 0; j < 8; j++)
            #pragma unroll
            for (int r = 0; r < 4; r++) acc[i][j][r] = 0.f;

    int NK = K / BK;

    auto prefetch = [&](int stage, int k0) {
        uint32_t sa = smem_u32(&As[stage][tid * AS_STRIDE]);
        #pragma unroll
        for (int j = 0; j < 4; j++)
            cp_async16(sa + j * 16, ga + k0 + 4 * j);
        uint32_t sb = smem_u32(&Bs[stage][brow * BS_STRIDE]);
        #pragma unroll
        for (int j = 0; j < 4; j++) {
            int c4 = bc0 + 8 * j;
            cp_async16(sb + c4 * 16, gb + (size_t)k0 * N + c4 * 4);
        }
        asm volatile("cp.async.commit_group;");
    };

    prefetch(0, 0);

    for (int kt = 0; kt < NK; kt++) {
        if (kt + 1 < NK) {
            prefetch((kt + 1) & 1, (kt + 1) * BK);
            asm volatile("cp.async.wait_group 1;");
        } else {
            asm volatile("cp.async.wait_group 0;");
        }
        __syncthreads();
        int st = kt & 1;
        const float* as = As[st];
        const float* bs = Bs[st];
        #pragma unroll
        for (int ks = 0; ks < BK; ks += 8) {
            uint32_t af[4][4], bf[8][2];
            #pragma unroll
            for (int mt = 0; mt < 4; mt++) {
                int r0 = wm + mt * 16 + g;
                af[mt][0] = cvt_tf32(as[r0 * AS_STRIDE + ks + l4]);
                af[mt][1] = cvt_tf32(as[(r0 + 8) * AS_STRIDE + ks + l4]);
                af[mt][2] = cvt_tf32(as[r0 * AS_STRIDE + ks + l4 + 4]);
                af[mt][3] = cvt_tf32(as[(r0 + 8) * AS_STRIDE + ks + l4 + 4]);
            }
            #pragma unroll
            for (int nt = 0; nt < 8; nt++) {
                int col = wn + nt * 8 + g;
                bf[nt][0] = cvt_tf32(bs[(ks + l4) * BS_STRIDE + col]);
                bf[nt][1] = cvt_tf32(bs[(ks + l4 + 4) * BS_STRIDE + col]);
            }
            #pragma unroll
            for (int mt = 0; mt < 4; mt++)
                #pragma unroll
                for (int nt = 0; nt < 8; nt++) {
                    asm volatile(
                        "mma.sync.aligned.m16n8k8.row.col.f32.tf32.tf32.f32 "
                        "{%0,%1,%2,%3}, {%4,%5,%6,%7}, {%8,%9}, {%0,%1,%2,%3};"
                        : "+f"(acc[mt][nt][0]), "+f"(acc[mt][nt][1]),
                          "+f"(acc[mt][nt][2]), "+f"(acc[mt][nt][3])
                        : "r"(af[mt][0]), "r"(af[mt][1]), "r"(af[mt][2]), "r"(af[mt][3]),
                          "r"(bf[nt][0]), "r"(bf[nt][1]));
                }
        }
        __syncthreads();
    }

    // epilogue
    #pragma unroll
    for (int mt = 0; mt < 4; mt++) {
        int r0 = bm + wm + mt * 16 + g;
        #pragma unroll
        for (int nt = 0; nt < 8; nt++) {
            int col = bn + wn + nt * 8 + 2 * l4;
            float bv0 = bias[col], bv1 = bias[col + 1];
            #pragma unroll
            for (int h = 0; h < 2; h++) {
                int row = r0 + h * 8;
                size_t off = (size_t)row * N + col;
                float v0 = acc[mt][nt][2 * h + 0] + bv0;
                float v1 = acc[mt][nt][2 * h + 1] + bv1;
                if (EPI == 0) {
                    v0 = v0 / (1.f + expf(-v0));
                    v1 = v1 / (1.f + expf(-v1));
                } else {
                    v0 += res[off];
                    v1 += res[off + 1];
                }
                float2 o = make_float2(v0, v1);
                *(float2*)&C[off] = o;
            }
        }
    }
}

// ---------------- launch ----------------
extern "C" void kernel_launch(void* const* d_in, const int* in_sizes, int n_in,
                              void* d_out, int out_size) {
    const float* x      = (const float*)d_in[0];
    const float* ln_g   = (const float*)d_in[1];
    const float* ln_b   = (const float*)d_in[2];
    const float* phazor = (const float*)d_in[3];
    const float* phinit = (const float*)d_in[4];
    const float* w1     = (const float*)d_in[5];
    const float* b1     = (const float*)d_in[6];
    const float* w2     = (const float*)d_in[7];
    const float* b2     = (const float*)d_in[8];
    const float* lre    = (const float*)d_in[9];
    const float* lim    = (const float*)d_in[10];
    float* out = (float*)d_out;

    float *hln, *y, *h2, *act;
    cudaGetSymbolAddress((void**)&hln, g_hln);
    cudaGetSymbolAddress((void**)&y,   g_y);
    cudaGetSymbolAddress((void**)&h2,  g_h2);
    cudaGetSymbolAddress((void**)&act, g_act);

    phazor_prep<<<1, DIM_>>>(phazor, phinit);
    ln_kernel<<<NTOK, 256>>>(x, ln_g, ln_b, hln);
    conv_phase1<<<B_ * NC, DIM_>>>(hln);
    conv_phase2<<<B_, DIM_>>>();
    conv_phase3<<<B_ * NC, DIM_>>>(hln, x, lre, lim, y);
    ln_kernel<<<NTOK, 256>>>(y, ln_g, ln_b, h2);

    dim3 g1(DFF_ / BN, NTOK / BM);
    tc_gemm<0><<<g1, 128>>>(h2, w1, b1, nullptr, act, NTOK, DFF_, DIM_);
    dim3 g2(DIM_ / BN, NTOK / BM);
    tc_gemm<1><<<g2, 128>>>(act, w2, b2, y, out, NTOK, DIM_, DFF_);
}

// round 4
// speedup vs baseline: 5.2015x; 2.1215x over previous
#include <cuda_runtime.h>
#include <cuda_fp16.h>
#include <math.h>
#include <stdint.h>

// Problem constants
#define B_   4
#define L_   2048
#define DIM_ 1024
#define DFF_ 4096
#define NTOK (B_ * L_)            // 8192 rows
#define CS   64                    // conv chunk size
#define NC   (L_ / CS)             // 32 chunks

// -------- scratch (static __device__ — no allocations allowed) --------
__device__ float   g_hln[(size_t)NTOK * DIM_];
__device__ float   g_y  [(size_t)NTOK * DIM_];
__device__ __half  g_h2h[(size_t)NTOK * DIM_];   // LN2 out, fp16
__device__ __half  g_act[(size_t)NTOK * DFF_];   // SiLU out, fp16
__device__ __half  g_w1h[(size_t)DFF_ * DIM_];   // w1^T fp16 [N=4096,K=1024]
__device__ __half  g_w2h[(size_t)DIM_ * DFF_];   // w2^T fp16 [N=1024,K=4096]
__device__ float2  g_carry[B_ * NC * DIM_];
__device__ float2  g_zin  [B_ * NC * DIM_];
__device__ float2  g_p    [DIM_];
__device__ float2  g_pinit[DIM_];
__device__ float2  g_p64  [DIM_];

// ================= helpers =================
__device__ __forceinline__ uint32_t smem_u32(const void* p) {
    return (uint32_t)__cvta_generic_to_shared(p);
}
__device__ __forceinline__ void cp_async16(uint32_t saddr, const void* gptr) {
    asm volatile("cp.async.cg.shared.global [%0], [%1], 16;" :: "r"(saddr), "l"(gptr));
}
#define CP_COMMIT()  asm volatile("cp.async.commit_group;" ::: "memory")
#define CP_WAIT(n)   asm volatile("cp.async.wait_group %0;" :: "n"(n) : "memory")

// ================= phazor precompute =================
__global__ void phazor_prep(const float* __restrict__ phazor,
                            const float* __restrict__ phazor_init) {
    int d = blockIdx.x * blockDim.x + threadIdx.x;
    if (d >= DIM_) return;
    float pr = phazor[2 * d], pim = phazor[2 * d + 1];
    float pa = sqrtf(pr * pr + pim * pim);
    float s = expf(-pa) / pa;
    float2 p = make_float2(pr * s, pim * s);
    g_p[d] = p;
    g_pinit[d] = make_float2(phazor_init[2 * d], phazor_init[2 * d + 1]);
    float2 q = p;
    #pragma unroll
    for (int i = 0; i < 6; i++) {
        float nr = q.x * q.x - q.y * q.y;
        q.y = 2.f * q.x * q.y;
        q.x = nr;
    }
    g_p64[d] = q;
}

// ================= layernorm (fp32 out / fp16 out) =================
template <int HALF_OUT>
__global__ void ln_kernel_t(const float* __restrict__ x, const float* __restrict__ g,
                            const float* __restrict__ bb, float* __restrict__ out32,
                            __half* __restrict__ out16) {
    int row = blockIdx.x;
    int tid = threadIdx.x;
    const float4* xr = (const float4*)(x + (size_t)row * DIM_);
    float4 v = xr[tid];
    float s  = v.x + v.y + v.z + v.w;
    float ss = v.x * v.x + v.y * v.y + v.z * v.z + v.w * v.w;
    #pragma unroll
    for (int o = 16; o > 0; o >>= 1) {
        s  += __shfl_xor_sync(0xffffffffu, s, o);
        ss += __shfl_xor_sync(0xffffffffu, ss, o);
    }
    __shared__ float sh[16];
    int w = tid >> 5;
    if ((tid & 31) == 0) { sh[w] = s; sh[w + 8] = ss; }
    __syncthreads();
    if (tid < 32) {
        float a = (tid < 8) ? sh[tid] : 0.f;
        float c = (tid < 8) ? sh[tid + 8] : 0.f;
        #pragma unroll
        for (int o = 4; o > 0; o >>= 1) {
            a += __shfl_xor_sync(0xffffffffu, a, o);
            c += __shfl_xor_sync(0xffffffffu, c, o);
        }
        if (tid == 0) { sh[0] = a; sh[1] = c; }
    }
    __syncthreads();
    float mu  = sh[0] * (1.f / DIM_);
    float var = sh[1] * (1.f / DIM_) - mu * mu;
    float inv = rsqrtf(var + 1e-5f);
    float4 gv = ((const float4*)g)[tid];
    float4 bv = ((const float4*)bb)[tid];
    float4 o4;
    o4.x = (v.x - mu) * inv * gv.x + bv.x;
    o4.y = (v.y - mu) * inv * gv.y + bv.y;
    o4.z = (v.z - mu) * inv * gv.z + bv.z;
    o4.w = (v.w - mu) * inv * gv.w + bv.w;
    if (HALF_OUT) {
        __half2 h0 = __floats2half2_rn(o4.x, o4.y);
        __half2 h1 = __floats2half2_rn(o4.z, o4.w);
        uint2 pk = make_uint2(*(uint32_t*)&h0, *(uint32_t*)&h1);
        *(uint2*)(out16 + (size_t)row * DIM_ + tid * 4) = pk;
    } else {
        ((float4*)(out32 + (size_t)row * DIM_))[tid] = o4;
    }
}

// ================= spiral conv: 3-phase chunked scan =================
__global__ void conv_phase1(const float* __restrict__ h) {
    int b = blockIdx.x >> 5, c = blockIdx.x & 31, d = threadIdx.x;
    float2 p = g_p[d];
    float zr = 0.f, zi = 0.f;
    const float* hp = h + ((size_t)b * L_ + c * CS) * DIM_ + d;
    #pragma unroll 4
    for (int j = 0; j < CS; j++) {
        float hv = hp[(size_t)j * DIM_];
        float nr = p.x * zr - p.y * zi + hv;
        zi = p.x * zi + p.y * zr;
        zr = nr;
    }
    g_carry[(b * NC + c) * DIM_ + d] = make_float2(zr, zi);
}

__global__ void conv_phase2() {
    int b = blockIdx.x;
    int d = blockIdx.y * 256 + threadIdx.x;
    float2 pc = g_p64[d];
    float2 cv[NC];
    #pragma unroll
    for (int c = 0; c < NC; c++) cv[c] = g_carry[(b * NC + c) * DIM_ + d];
    float zr = 0.f, zi = 0.f;
    #pragma unroll
    for (int c = 0; c < NC; c++) {
        g_zin[(b * NC + c) * DIM_ + d] = make_float2(zr, zi);
        float nr = pc.x * zr - pc.y * zi + cv[c].x;
        zi = pc.x * zi + pc.y * zr + cv[c].y;
        zr = nr;
    }
}

__global__ void conv_phase3(const float* __restrict__ h, const float* __restrict__ x,
                            const float* __restrict__ lre, const float* __restrict__ lim,
                            float* __restrict__ y) {
    int b = blockIdx.x >> 5, c = blockIdx.x & 31, d = threadIdx.x;
    float2 p  = g_p[d];
    float2 pi = g_pinit[d];
    float2 pc = g_p64[d];
    float2 z  = g_zin[(b * NC + c) * DIM_ + d];
    float twr = 1.f, twi = 0.f;
    for (int i = 0; i < c; i++) {
        float nr = twr * pc.x - twi * pc.y;
        twi = twr * pc.y + twi * pc.x;
        twr = nr;
    }
    float pwr = twr * p.x - twi * p.y;
    float pwi = twr * p.y + twi * p.x;
    float lr = lre[b * DIM_ + d], li = lim[b * DIM_ + d];
    size_t base = ((size_t)b * L_ + c * CS) * DIM_ + d;
    #pragma unroll 4
    for (int j = 0; j < CS; j++) {
        float hv = h[base + (size_t)j * DIM_];
        float nr = p.x * z.x - p.y * z.y + hv;
        z.y = p.x * z.y + p.y * z.x;
        z.x = nr;
        float val = pi.x * z.x - pi.y * z.y + lr * pwr - li * pwi;
        y[base + (size_t)j * DIM_] = val + x[base + (size_t)j * DIM_];
        float npr = pwr * p.x - pwi * p.y;
        pwi = pwr * p.y + pwi * p.x;
        pwr = npr;
    }
}

// ======== weight transpose + cast ([K,N] fp32 -> [N,K] fp16) ========
__global__ void transpose_h(const float* __restrict__ in, __half* __restrict__ out,
                            int R, int Ccols) {
    __shared__ float t[32][33];
    int bx = blockIdx.x * 32, by = blockIdx.y * 32;
    int tx = threadIdx.x, ty = threadIdx.y;
    #pragma unroll
    for (int j = 0; j < 32; j += 8)
        t[ty + j][tx] = in[(size_t)(by + ty + j) * Ccols + bx + tx];
    __syncthreads();
    #pragma unroll
    for (int j = 0; j < 32; j += 8)
        out[(size_t)(bx + ty + j) * R + by + tx] = __float2half(t[tx][ty + j]);
}

// ================= fp16 tensor-core GEMM (mma.sync m16n8k16) =================
// Block 128x256, BK=32 (fp16), 8 warps x (64x64), 3-stage cp.async ring.
// EPI==0: act(half) = silu(acc + bias);  EPI==1: out(f32) = acc + bias + res
#define TM 128
#define TN 256
#define TBK 32
#define ROW_H 72                         // padded stride in halves (144B, 16B-aligned)
#define A_HALFS (TM * ROW_H)             // 9216 halves = 18432 B
#define B_HALFS (TN * ROW_H)             // 18432 halves = 36864 B
#define STG_HALFS (A_HALFS + B_HALFS)    // 27648 halves = 55296 B
#define GEMM_SMEM (3 * STG_HALFS * 2)    // 165888 B

template <int EPI>
__global__ __launch_bounds__(256, 1) void hgemm(
    const __half* __restrict__ A, const __half* __restrict__ Bt,
    const float* __restrict__ bias, const float* __restrict__ res,
    __half* __restrict__ Ch, float* __restrict__ Cf, int M, int N, int K) {
    extern __shared__ __half sm[];
    int tid = threadIdx.x, wid = tid >> 5, lane = tid & 31;
    int g = lane >> 2, l4 = lane & 3;
    int wm = (wid & 1) * 64;              // 2x4 warp grid
    int wn = (wid >> 1) * 64;
    int bm = blockIdx.y * TM, bn = blockIdx.x * TN;
    const int NK = K / TBK;

    // global-load assignments (per stage):
    // A: 512 16B chunks; thread handles 2.  row = c>>2 (0..127), kc = c&3.
    // B: 1024 16B chunks; thread handles 4. row = c>>2 (0..255), kc = c&3.
    auto load_stage = [&](int s, int k0) {
        uint32_t base = smem_u32(sm + (size_t)s * STG_HALFS);
        #pragma unroll
        for (int i = 0; i < 2; i++) {
            int c = tid + i * 256;
            int row = c >> 2, kc = c & 3;
            cp_async16(base + row * 144 + kc * 16,
                       A + (size_t)(bm + row) * K + k0 + kc * 8);
        }
        uint32_t bb = base + A_HALFS * 2;
        #pragma unroll
        for (int i = 0; i < 4; i++) {
            int c = tid + i * 256;
            int row = c >> 2, kc = c & 3;
            cp_async16(bb + row * 144 + kc * 16,
                       Bt + (size_t)(bn + row) * K + k0 + kc * 8);
        }
    };

    float acc[4][8][4];
    #pragma unroll
    for (int i = 0; i < 4; i++)
        #pragma unroll
        for (int j = 0; j < 8; j++)
            #pragma unroll
            for (int r = 0; r < 4; r++) acc[i][j][r] = 0.f;

    load_stage(0, 0);       CP_COMMIT();
    load_stage(1, TBK);     CP_COMMIT();

    for (int kt = 0; kt < NK; kt++) {
        if (kt + 1 < NK) CP_WAIT(1); else CP_WAIT(0);
        __syncthreads();
        const __half* as = sm + (size_t)(kt % 3) * STG_HALFS;
        const __half* bs = as + A_HALFS;
        #pragma unroll
        for (int ks = 0; ks < TBK; ks += 16) {
            uint32_t af[4][4], bf[8][2];
            #pragma unroll
            for (int mt = 0; mt < 4; mt++) {
                int r0 = wm + mt * 16 + g;
                af[mt][0] = *(const uint32_t*)&as[r0 * ROW_H + ks + 2 * l4];
                af[mt][1] = *(const uint32_t*)&as[(r0 + 8) * ROW_H + ks + 2 * l4];
                af[mt][2] = *(const uint32_t*)&as[r0 * ROW_H + ks + 8 + 2 * l4];
                af[mt][3] = *(const uint32_t*)&as[(r0 + 8) * ROW_H + ks + 8 + 2 * l4];
            }
            #pragma unroll
            for (int nt = 0; nt < 8; nt++) {
                int n0 = wn + nt * 8 + g;
                bf[nt][0] = *(const uint32_t*)&bs[n0 * ROW_H + ks + 2 * l4];
                bf[nt][1] = *(const uint32_t*)&bs[n0 * ROW_H + ks + 8 + 2 * l4];
            }
            #pragma unroll
            for (int mt = 0; mt < 4; mt++)
                #pragma unroll
                for (int nt = 0; nt < 8; nt++) {
                    asm volatile(
                        "mma.sync.aligned.m16n8k16.row.col.f32.f16.f16.f32 "
                        "{%0,%1,%2,%3}, {%4,%5,%6,%7}, {%8,%9}, {%0,%1,%2,%3};"
                        : "+f"(acc[mt][nt][0]), "+f"(acc[mt][nt][1]),
                          "+f"(acc[mt][nt][2]), "+f"(acc[mt][nt][3])
                        : "r"(af[mt][0]), "r"(af[mt][1]), "r"(af[mt][2]), "r"(af[mt][3]),
                          "r"(bf[nt][0]), "r"(bf[nt][1]));
                }
        }
        __syncthreads();
        if (kt + 2 < NK) { load_stage((kt + 2) % 3, (kt + 2) * TBK); }
        CP_COMMIT();
    }

    // ---- epilogue ----
    #pragma unroll
    for (int mt = 0; mt < 4; mt++) {
        int r0 = bm + wm + mt * 16 + g;
        #pragma unroll
        for (int nt = 0; nt < 8; nt++) {
            int col = bn + wn + nt * 8 + 2 * l4;
            float bv0 = bias[col], bv1 = bias[col + 1];
            #pragma unroll
            for (int h = 0; h < 2; h++) {
                int row = r0 + h * 8;
                size_t off = (size_t)row * N + col;
                float v0 = acc[mt][nt][2 * h + 0] + bv0;
                float v1 = acc[mt][nt][2 * h + 1] + bv1;
                if (EPI == 0) {
                    v0 = v0 / (1.f + expf(-v0));
                    v1 = v1 / (1.f + expf(-v1));
                    __half2 hv = __floats2half2_rn(v0, v1);
                    *(__half2*)&Ch[off] = hv;
                } else {
                    v0 += res[off];
                    v1 += res[off + 1];
                    *(float2*)&Cf[off] = make_float2(v0, v1);
                }
            }
        }
    }
}

// ================= launch =================
extern "C" void kernel_launch(void* const* d_in, const int* in_sizes, int n_in,
                              void* d_out, int out_size) {
    const float* x      = (const float*)d_in[0];
    const float* ln_g   = (const float*)d_in[1];
    const float* ln_b   = (const float*)d_in[2];
    const float* phazor = (const float*)d_in[3];
    const float* phinit = (const float*)d_in[4];
    const float* w1     = (const float*)d_in[5];
    const float* b1     = (const float*)d_in[6];
    const float* w2     = (const float*)d_in[7];
    const float* b2     = (const float*)d_in[8];
    const float* lre    = (const float*)d_in[9];
    const float* lim    = (const float*)d_in[10];
    float* out = (float*)d_out;

    float *hln, *y;
    __half *h2h, *act, *w1h, *w2h;
    cudaGetSymbolAddress((void**)&hln, g_hln);
    cudaGetSymbolAddress((void**)&y,   g_y);
    cudaGetSymbolAddress((void**)&h2h, g_h2h);
    cudaGetSymbolAddress((void**)&act, g_act);
    cudaGetSymbolAddress((void**)&w1h, g_w1h);
    cudaGetSymbolAddress((void**)&w2h, g_w2h);

    cudaFuncSetAttribute(hgemm<0>, cudaFuncAttributeMaxDynamicSharedMemorySize, GEMM_SMEM);
    cudaFuncSetAttribute(hgemm<1>, cudaFuncAttributeMaxDynamicSharedMemorySize, GEMM_SMEM);

    // weights: [K,N] fp32 -> [N,K] fp16
    transpose_h<<<dim3(DFF_ / 32, DIM_ / 32), dim3(32, 8)>>>(w1, w1h, DIM_, DFF_);
    transpose_h<<<dim3(DIM_ / 32, DFF_ / 32), dim3(32, 8)>>>(w2, w2h, DFF_, DIM_);

    phazor_prep<<<1, DIM_>>>(phazor, phinit);
    ln_kernel_t<0><<<NTOK, 256>>>(x, ln_g, ln_b, hln, nullptr);
    conv_phase1<<<B_ * NC, DIM_>>>(hln);
    conv_phase2<<<dim3(B_, DIM_ / 256), 256>>>();
    conv_phase3<<<B_ * NC, DIM_>>>(hln, x, lre, lim, y);
    ln_kernel_t<1><<<NTOK, 256>>>(y, ln_g, ln_b, nullptr, h2h);

    dim3 g1(DFF_ / TN, NTOK / TM);   // 16 x 64
    hgemm<0><<<g1, 256, GEMM_SMEM>>>(h2h, w1h, b1, nullptr, act, nullptr, NTOK, DFF_, DIM_);
    dim3 g2(DIM_ / TN, NTOK / TM);   // 4 x 64
    hgemm<1><<<g2, 256, GEMM_SMEM>>>(act, w2h, b2, y, nullptr, out, NTOK, DIM_, DFF_);
}

// round 5
// speedup vs baseline: 5.2491x; 1.0092x over previous
#include <cuda_runtime.h>
#include <cuda_fp16.h>
#include <math.h>
#include <stdint.h>

// Problem constants
#define B_   4
#define L_   2048
#define DIM_ 1024
#define DFF_ 4096
#define NTOK (B_ * L_)            // 8192 rows
#define CS   64                    // conv chunk size
#define NC   (L_ / CS)             // 32 chunks

// -------- scratch (static __device__ — no allocations allowed) --------
__device__ float   g_y  [(size_t)NTOK * DIM_];
__device__ __half  g_h2h[(size_t)NTOK * DIM_];   // LN2 out, fp16
__device__ __half  g_act[(size_t)NTOK * DFF_];   // SiLU out, fp16
__device__ __half  g_w1h[(size_t)DFF_ * DIM_];   // w1^T fp16 [N=4096,K=1024]
__device__ __half  g_w2h[(size_t)DIM_ * DFF_];   // w2^T fp16 [N=1024,K=4096]
__device__ float2  g_stat[NTOK];                 // LN1 (mu, rstd) per row
__device__ float2  g_carry[B_ * NC * DIM_];
__device__ float2  g_zin  [B_ * NC * DIM_];
__device__ float2  g_p    [DIM_];
__device__ float2  g_pinit[DIM_];
__device__ float2  g_p64  [DIM_];

// ================= helpers =================
__device__ __forceinline__ uint32_t smem_u32(const void* p) {
    return (uint32_t)__cvta_generic_to_shared(p);
}
__device__ __forceinline__ void cp_async16(uint32_t saddr, const void* gptr) {
    asm volatile("cp.async.cg.shared.global [%0], [%1], 16;" :: "r"(saddr), "l"(gptr));
}
#define CP_COMMIT()  asm volatile("cp.async.commit_group;" ::: "memory")
#define CP_WAIT(n)   asm volatile("cp.async.wait_group %0;" :: "n"(n) : "memory")
#define LDSM_X4(r0, r1, r2, r3, addr) \
    asm volatile("ldmatrix.sync.aligned.m8n8.x4.shared.b16 {%0,%1,%2,%3}, [%4];" \
                 : "=r"(r0), "=r"(r1), "=r"(r2), "=r"(r3) : "r"(addr))

// ================= phazor precompute =================
__global__ void phazor_prep(const float* __restrict__ phazor,
                            const float* __restrict__ phazor_init) {
    int d = blockIdx.x * blockDim.x + threadIdx.x;
    if (d >= DIM_) return;
    float pr = phazor[2 * d], pim = phazor[2 * d + 1];
    float pa = sqrtf(pr * pr + pim * pim);
    float s = expf(-pa) / pa;
    float2 p = make_float2(pr * s, pim * s);
    g_p[d] = p;
    g_pinit[d] = make_float2(phazor_init[2 * d], phazor_init[2 * d + 1]);
    float2 q = p;
    #pragma unroll
    for (int i = 0; i < 6; i++) {
        float nr = q.x * q.x - q.y * q.y;
        q.y = 2.f * q.x * q.y;
        q.x = nr;
    }
    g_p64[d] = q;
}

// ========== LN1 stats: per-row (mu, rstd) ==========
__global__ void ln_stats(const float* __restrict__ x) {
    int row = blockIdx.x;
    int tid = threadIdx.x;
    const float4* xr = (const float4*)(x + (size_t)row * DIM_);
    float4 v = xr[tid];
    float s  = v.x + v.y + v.z + v.w;
    float ss = v.x * v.x + v.y * v.y + v.z * v.z + v.w * v.w;
    #pragma unroll
    for (int o = 16; o > 0; o >>= 1) {
        s  += __shfl_xor_sync(0xffffffffu, s, o);
        ss += __shfl_xor_sync(0xffffffffu, ss, o);
    }
    __shared__ float sh[16];
    int w = tid >> 5;
    if ((tid & 31) == 0) { sh[w] = s; sh[w + 8] = ss; }
    __syncthreads();
    if (tid == 0) {
        float a = 0.f, c = 0.f;
        #pragma unroll
        for (int i = 0; i < 8; i++) { a += sh[i]; c += sh[i + 8]; }
        float mu = a * (1.f / DIM_);
        float var = c * (1.f / DIM_) - mu * mu;
        g_stat[row] = make_float2(mu, rsqrtf(var + 1e-5f));
    }
}

// ========== LN2 (fp32 in -> fp16 out) ==========
__global__ void ln2_kernel(const float* __restrict__ x, const float* __restrict__ g,
                           const float* __restrict__ bb, __half* __restrict__ out16) {
    int row = blockIdx.x;
    int tid = threadIdx.x;
    const float4* xr = (const float4*)(x + (size_t)row * DIM_);
    float4 v = xr[tid];
    float s  = v.x + v.y + v.z + v.w;
    float ss = v.x * v.x + v.y * v.y + v.z * v.z + v.w * v.w;
    #pragma unroll
    for (int o = 16; o > 0; o >>= 1) {
        s  += __shfl_xor_sync(0xffffffffu, s, o);
        ss += __shfl_xor_sync(0xffffffffu, ss, o);
    }
    __shared__ float sh[16];
    int w = tid >> 5;
    if ((tid & 31) == 0) { sh[w] = s; sh[w + 8] = ss; }
    __syncthreads();
    if (tid < 32) {
        float a = (tid < 8) ? sh[tid] : 0.f;
        float c = (tid < 8) ? sh[tid + 8] : 0.f;
        #pragma unroll
        for (int o = 4; o > 0; o >>= 1) {
            a += __shfl_xor_sync(0xffffffffu, a, o);
            c += __shfl_xor_sync(0xffffffffu, c, o);
        }
        if (tid == 0) { sh[0] = a; sh[1] = c; }
    }
    __syncthreads();
    float mu  = sh[0] * (1.f / DIM_);
    float var = sh[1] * (1.f / DIM_) - mu * mu;
    float inv = rsqrtf(var + 1e-5f);
    float4 gv = ((const float4*)g)[tid];
    float4 bv = ((const float4*)bb)[tid];
    __half2 h0 = __floats2half2_rn((v.x - mu) * inv * gv.x + bv.x,
                                   (v.y - mu) * inv * gv.y + bv.y);
    __half2 h1 = __floats2half2_rn((v.z - mu) * inv * gv.z + bv.z,
                                   (v.w - mu) * inv * gv.w + bv.w);
    uint2 pk = make_uint2(*(uint32_t*)&h0, *(uint32_t*)&h1);
    *(uint2*)(out16 + (size_t)row * DIM_ + tid * 4) = pk;
}

// ================= spiral conv: 3-phase chunked scan =================
// LN1 applied inline from x + stats (no materialized hln).
__global__ void conv_phase1(const float* __restrict__ x, const float* __restrict__ lng,
                            const float* __restrict__ lnb) {
    int b = blockIdx.x >> 5, c = blockIdx.x & 31, d = threadIdx.x;
    float2 p = g_p[d];
    float gd = lng[d], bd = lnb[d];
    float zr = 0.f, zi = 0.f;
    int row0 = b * L_ + c * CS;
    const float* xp = x + (size_t)row0 * DIM_ + d;
    #pragma unroll 4
    for (int j = 0; j < CS; j++) {
        float2 st = g_stat[row0 + j];
        float hv = (xp[(size_t)j * DIM_] - st.x) * st.y * gd + bd;
        float nr = p.x * zr - p.y * zi + hv;
        zi = p.x * zi + p.y * zr;
        zr = nr;
    }
    g_carry[(b * NC + c) * DIM_ + d] = make_float2(zr, zi);
}

__global__ void conv_phase2() {
    int b = blockIdx.x;
    int d = blockIdx.y * 256 + threadIdx.x;
    float2 pc = g_p64[d];
    float2 cv[NC];
    #pragma unroll
    for (int c = 0; c < NC; c++) cv[c] = g_carry[(b * NC + c) * DIM_ + d];
    float zr = 0.f, zi = 0.f;
    #pragma unroll
    for (int c = 0; c < NC; c++) {
        g_zin[(b * NC + c) * DIM_ + d] = make_float2(zr, zi);
        float nr = pc.x * zr - pc.y * zi + cv[c].x;
        zi = pc.x * zi + pc.y * zr + cv[c].y;
        zr = nr;
    }
}

__global__ void conv_phase3(const float* __restrict__ x, const float* __restrict__ lng,
                            const float* __restrict__ lnb,
                            const float* __restrict__ lre, const float* __restrict__ lim,
                            float* __restrict__ y) {
    int b = blockIdx.x >> 5, c = blockIdx.x & 31, d = threadIdx.x;
    float2 p  = g_p[d];
    float2 pi = g_pinit[d];
    float2 pc = g_p64[d];
    float2 z  = g_zin[(b * NC + c) * DIM_ + d];
    float gd = lng[d], bd = lnb[d];
    float twr = 1.f, twi = 0.f;
    for (int i = 0; i < c; i++) {
        float nr = twr * pc.x - twi * pc.y;
        twi = twr * pc.y + twi * pc.x;
        twr = nr;
    }
    float pwr = twr * p.x - twi * p.y;
    float pwi = twr * p.y + twi * p.x;
    float lr = lre[b * DIM_ + d], li = lim[b * DIM_ + d];
    int row0 = b * L_ + c * CS;
    size_t base = (size_t)row0 * DIM_ + d;
    #pragma unroll 4
    for (int j = 0; j < CS; j++) {
        float xv = x[base + (size_t)j * DIM_];
        float2 st = g_stat[row0 + j];
        float hv = (xv - st.x) * st.y * gd + bd;
        float nr = p.x * z.x - p.y * z.y + hv;
        z.y = p.x * z.y + p.y * z.x;
        z.x = nr;
        float val = pi.x * z.x - pi.y * z.y + lr * pwr - li * pwi;
        y[base + (size_t)j * DIM_] = val + xv;
        float npr = pwr * p.x - pwi * p.y;
        pwi = pwr * p.y + pwi * p.x;
        pwr = npr;
    }
}

// ======== weight transpose + cast ([K,N] fp32 -> [N,K] fp16) ========
__global__ void transpose_h(const float* __restrict__ in, __half* __restrict__ out,
                            int R, int Ccols) {
    __shared__ float t[32][33];
    int bx = blockIdx.x * 32, by = blockIdx.y * 32;
    int tx = threadIdx.x, ty = threadIdx.y;
    #pragma unroll
    for (int j = 0; j < 32; j += 8)
        t[ty + j][tx] = in[(size_t)(by + ty + j) * Ccols + bx + tx];
    __syncthreads();
    #pragma unroll
    for (int j = 0; j < 32; j += 8)
        out[(size_t)(bx + ty + j) * R + by + tx] = __float2half(t[tx][ty + j]);
}

// ================= fp16 tensor-core GEMM (mma.sync m16n8k16 + ldmatrix) ========
// Block 128x256, BK=32, 8 warps x (64x64), 3-stage cp.async ring.
// EPI==0: act(half) = silu(acc + bias);  EPI==1: out(f32) = acc + bias + res
#define TM 128
#define TN 256
#define TBK 32
#define ROW_H 72                         // padded stride in halves (144B)
#define A_HALFS (TM * ROW_H)
#define B_HALFS (TN * ROW_H)
#define STG_HALFS (A_HALFS + B_HALFS)
#define GEMM_SMEM (3 * STG_HALFS * 2)    // 165888 B

template <int EPI>
__global__ __launch_bounds__(256, 1) void hgemm(
    const __half* __restrict__ A, const __half* __restrict__ Bt,
    const float* __restrict__ bias, const float* __restrict__ res,
    __half* __restrict__ Ch, float* __restrict__ Cf, int M, int N, int K) {
    extern __shared__ __half sm[];
    int tid = threadIdx.x, wid = tid >> 5, lane = tid & 31;
    int g = lane >> 2, l4 = lane & 3;
    int wm = (wid & 1) * 64;              // 2x4 warp grid
    int wn = (wid >> 1) * 64;
    int bm = blockIdx.y * TM, bn = blockIdx.x * TN;
    const int NK = K / TBK;

    // ldmatrix per-lane byte offsets (relative to stage A/B bases, ks=0)
    int mat = lane >> 3, rr = lane & 7;
    uint32_t aoff[4], boff[4];
    #pragma unroll
    for (int mt = 0; mt < 4; mt++)
        aoff[mt] = (uint32_t)((wm + mt * 16 + (mat & 1) * 8 + rr) * 144 + (mat >> 1) * 16);
    #pragma unroll
    for (int np = 0; np < 4; np++)
        boff[np] = (uint32_t)((wn + np * 16 + (mat >> 1) * 8 + rr) * 144 + (mat & 1) * 16);

    auto load_stage = [&](int s, int k0) {
        uint32_t base = smem_u32(sm + (size_t)s * STG_HALFS);
        #pragma unroll
        for (int i = 0; i < 2; i++) {
            int c = tid + i * 256;
            int row = c >> 2, kc = c & 3;
            cp_async16(base + row * 144 + kc * 16,
                       A + (size_t)(bm + row) * K + k0 + kc * 8);
        }
        uint32_t bb = base + A_HALFS * 2;
        #pragma unroll
        for (int i = 0; i < 4; i++) {
            int c = tid + i * 256;
            int row = c >> 2, kc = c & 3;
            cp_async16(bb + row * 144 + kc * 16,
                       Bt + (size_t)(bn + row) * K + k0 + kc * 8);
        }
    };

    float acc[4][8][4];
    #pragma unroll
    for (int i = 0; i < 4; i++)
        #pragma unroll
        for (int j = 0; j < 8; j++)
            #pragma unroll
            for (int r = 0; r < 4; r++) acc[i][j][r] = 0.f;

    load_stage(0, 0);       CP_COMMIT();
    load_stage(1, TBK);     CP_COMMIT();

    for (int kt = 0; kt < NK; kt++) {
        if (kt + 1 < NK) CP_WAIT(1); else CP_WAIT(0);
        __syncthreads();
        uint32_t sa = smem_u32(sm + (size_t)(kt % 3) * STG_HALFS);
        uint32_t sb = sa + A_HALFS * 2;
        #pragma unroll
        for (int ks = 0; ks < TBK; ks += 16) {
            uint32_t af[4][4], bf[8][2];
            #pragma unroll
            for (int mt = 0; mt < 4; mt++)
                LDSM_X4(af[mt][0], af[mt][1], af[mt][2], af[mt][3],
                        sa + aoff[mt] + ks * 2);
            #pragma unroll
            for (int np = 0; np < 4; np++)
                LDSM_X4(bf[2 * np][0], bf[2 * np][1], bf[2 * np + 1][0], bf[2 * np + 1][1],
                        sb + boff[np] + ks * 2);
            #pragma unroll
            for (int mt = 0; mt < 4; mt++)
                #pragma unroll
                for (int nt = 0; nt < 8; nt++) {
                    asm volatile(
                        "mma.sync.aligned.m16n8k16.row.col.f32.f16.f16.f32 "
                        "{%0,%1,%2,%3}, {%4,%5,%6,%7}, {%8,%9}, {%0,%1,%2,%3};"
                        : "+f"(acc[mt][nt][0]), "+f"(acc[mt][nt][1]),
                          "+f"(acc[mt][nt][2]), "+f"(acc[mt][nt][3])
                        : "r"(af[mt][0]), "r"(af[mt][1]), "r"(af[mt][2]), "r"(af[mt][3]),
                          "r"(bf[nt][0]), "r"(bf[nt][1]));
                }
        }
        __syncthreads();
        if (kt + 2 < NK) { load_stage((kt + 2) % 3, (kt + 2) * TBK); }
        CP_COMMIT();
    }

    // ---- epilogue ----
    #pragma unroll
    for (int mt = 0; mt < 4; mt++) {
        int r0 = bm + wm + mt * 16 + g;
        #pragma unroll
        for (int nt = 0; nt < 8; nt++) {
            int col = bn + wn + nt * 8 + 2 * l4;
            float bv0 = bias[col], bv1 = bias[col + 1];
            #pragma unroll
            for (int h = 0; h < 2; h++) {
                int row = r0 + h * 8;
                size_t off = (size_t)row * N + col;
                float v0 = acc[mt][nt][2 * h + 0] + bv0;
                float v1 = acc[mt][nt][2 * h + 1] + bv1;
                if (EPI == 0) {
                    v0 = v0 / (1.f + expf(-v0));
                    v1 = v1 / (1.f + expf(-v1));
                    __half2 hv = __floats2half2_rn(v0, v1);
                    *(__half2*)&Ch[off] = hv;
                } else {
                    v0 += res[off];
                    v1 += res[off + 1];
                    *(float2*)&Cf[off] = make_float2(v0, v1);
                }
            }
        }
    }
}

// ================= launch =================
extern "C" void kernel_launch(void* const* d_in, const int* in_sizes, int n_in,
                              void* d_out, int out_size) {
    const float* x      = (const float*)d_in[0];
    const float* ln_g   = (const float*)d_in[1];
    const float* ln_b   = (const float*)d_in[2];
    const float* phazor = (const float*)d_in[3];
    const float* phinit = (const float*)d_in[4];
    const float* w1     = (const float*)d_in[5];
    const float* b1     = (const float*)d_in[6];
    const float* w2     = (const float*)d_in[7];
    const float* b2     = (const float*)d_in[8];
    const float* lre    = (const float*)d_in[9];
    const float* lim    = (const float*)d_in[10];
    float* out = (float*)d_out;

    float *y;
    __half *h2h, *act, *w1h, *w2h;
    cudaGetSymbolAddress((void**)&y,   g_y);
    cudaGetSymbolAddress((void**)&h2h, g_h2h);
    cudaGetSymbolAddress((void**)&act, g_act);
    cudaGetSymbolAddress((void**)&w1h, g_w1h);
    cudaGetSymbolAddress((void**)&w2h, g_w2h);

    cudaFuncSetAttribute(hgemm<0>, cudaFuncAttributeMaxDynamicSharedMemorySize, GEMM_SMEM);
    cudaFuncSetAttribute(hgemm<1>, cudaFuncAttributeMaxDynamicSharedMemorySize, GEMM_SMEM);

    transpose_h<<<dim3(DFF_ / 32, DIM_ / 32), dim3(32, 8)>>>(w1, w1h, DIM_, DFF_);
    transpose_h<<<dim3(DIM_ / 32, DFF_ / 32), dim3(32, 8)>>>(w2, w2h, DFF_, DIM_);

    phazor_prep<<<1, DIM_>>>(phazor, phinit);
    ln_stats<<<NTOK, 256>>>(x);
    conv_phase1<<<B_ * NC, DIM_>>>(x, ln_g, ln_b);
    conv_phase2<<<dim3(B_, DIM_ / 256), 256>>>();
    conv_phase3<<<B_ * NC, DIM_>>>(x, ln_g, ln_b, lre, lim, y);
    ln2_kernel<<<NTOK, 256>>>(y, ln_g, ln_b, h2h);

    dim3 g1(DFF_ / TN, NTOK / TM);   // 16 x 64
    hgemm<0><<<g1, 256, GEMM_SMEM>>>(h2h, w1h, b1, nullptr, act, nullptr, NTOK, DFF_, DIM_);
    dim3 g2(DIM_ / TN, NTOK / TM);   // 4 x 64
    hgemm<1><<<g2, 256, GEMM_SMEM>>>(act, w2h, b2, y, nullptr, out, NTOK, DIM_, DFF_);
}

// round 6
// speedup vs baseline: 5.5663x; 1.0604x over previous
#include <cuda_runtime.h>
#include <cuda_fp16.h>
#include <math.h>
#include <stdint.h>

// Problem constants
#define B_   4
#define L_   2048
#define DIM_ 1024
#define DFF_ 4096
#define NTOK (B_ * L_)            // 8192 rows
#define CS   64                    // conv chunk size
#define NC   (L_ / CS)             // 32 chunks

// -------- scratch (static __device__ — no allocations allowed) --------
__device__ float   g_y  [(size_t)NTOK * DIM_];
__device__ __half  g_h2h[(size_t)NTOK * DIM_];   // LN2 out, fp16
__device__ __half  g_act[(size_t)NTOK * DFF_];   // SiLU out, fp16
__device__ __half  g_w1h[(size_t)DFF_ * DIM_];   // w1^T fp16 [N=4096,K=1024]
__device__ __half  g_w2h[(size_t)DIM_ * DFF_];   // w2^T fp16 [N=1024,K=4096]
__device__ float2  g_stat[NTOK];                 // LN1 (mu, rstd) per row
__device__ float2  g_carry[B_ * NC * DIM_];
__device__ float2  g_zin  [B_ * NC * DIM_];
__device__ float2  g_p    [DIM_];
__device__ float2  g_pinit[DIM_];
__device__ float2  g_p64  [DIM_];

// ================= helpers =================
__device__ __forceinline__ uint32_t smem_u32(const void* p) {
    return (uint32_t)__cvta_generic_to_shared(p);
}
__device__ __forceinline__ void cp_async16(uint32_t saddr, const void* gptr) {
    asm volatile("cp.async.cg.shared.global [%0], [%1], 16;" :: "r"(saddr), "l"(gptr));
}
#define CP_COMMIT()  asm volatile("cp.async.commit_group;" ::: "memory")
#define CP_WAIT(n)   asm volatile("cp.async.wait_group %0;" :: "n"(n) : "memory")
#define LDSM_X4(r0, r1, r2, r3, addr) \
    asm volatile("ldmatrix.sync.aligned.m8n8.x4.shared.b16 {%0,%1,%2,%3}, [%4];" \
                 : "=r"(r0), "=r"(r1), "=r"(r2), "=r"(r3) : "r"(addr))

// ================= phazor precompute =================
__global__ void phazor_prep(const float* __restrict__ phazor,
                            const float* __restrict__ phazor_init) {
    int d = blockIdx.x * blockDim.x + threadIdx.x;
    if (d >= DIM_) return;
    float pr = phazor[2 * d], pim = phazor[2 * d + 1];
    float pa = sqrtf(pr * pr + pim * pim);
    float s = expf(-pa) / pa;
    float2 p = make_float2(pr * s, pim * s);
    g_p[d] = p;
    g_pinit[d] = make_float2(phazor_init[2 * d], phazor_init[2 * d + 1]);
    float2 q = p;
    #pragma unroll
    for (int i = 0; i < 6; i++) {
        float nr = q.x * q.x - q.y * q.y;
        q.y = 2.f * q.x * q.y;
        q.x = nr;
    }
    g_p64[d] = q;
}

// ========== LN1 stats: warp per row ==========
__global__ void ln_stats(const float* __restrict__ x) {
    int row = blockIdx.x * 8 + (threadIdx.x >> 5);
    int lane = threadIdx.x & 31;
    const float4* xr = (const float4*)(x + (size_t)row * DIM_);
    float s = 0.f, ss = 0.f;
    #pragma unroll
    for (int i = 0; i < 8; i++) {
        float4 v = xr[lane + 32 * i];
        s  += v.x + v.y + v.z + v.w;
        ss += v.x * v.x + v.y * v.y + v.z * v.z + v.w * v.w;
    }
    #pragma unroll
    for (int o = 16; o > 0; o >>= 1) {
        s  += __shfl_xor_sync(0xffffffffu, s, o);
        ss += __shfl_xor_sync(0xffffffffu, ss, o);
    }
    if (lane == 0) {
        float mu = s * (1.f / DIM_);
        float var = ss * (1.f / DIM_) - mu * mu;
        g_stat[row] = make_float2(mu, rsqrtf(var + 1e-5f));
    }
}

// ========== LN2 (warp per row, fp32 in -> fp16 out) ==========
__global__ void ln2_kernel(const float* __restrict__ x, const float* __restrict__ g,
                           const float* __restrict__ bb, __half* __restrict__ out16) {
    int row = blockIdx.x * 8 + (threadIdx.x >> 5);
    int lane = threadIdx.x & 31;
    const float4* xr = (const float4*)(x + (size_t)row * DIM_);
    float4 vv[8];
    float s = 0.f, ss = 0.f;
    #pragma unroll
    for (int i = 0; i < 8; i++) {
        float4 v = xr[lane + 32 * i];
        vv[i] = v;
        s  += v.x + v.y + v.z + v.w;
        ss += v.x * v.x + v.y * v.y + v.z * v.z + v.w * v.w;
    }
    #pragma unroll
    for (int o = 16; o > 0; o >>= 1) {
        s  += __shfl_xor_sync(0xffffffffu, s, o);
        ss += __shfl_xor_sync(0xffffffffu, ss, o);
    }
    float mu  = s * (1.f / DIM_);
    float var = ss * (1.f / DIM_) - mu * mu;
    float inv = rsqrtf(var + 1e-5f);
    #pragma unroll
    for (int i = 0; i < 8; i++) {
        float4 gv = ((const float4*)g)[lane + 32 * i];
        float4 bv = ((const float4*)bb)[lane + 32 * i];
        float4 v = vv[i];
        __half2 h0 = __floats2half2_rn((v.x - mu) * inv * gv.x + bv.x,
                                       (v.y - mu) * inv * gv.y + bv.y);
        __half2 h1 = __floats2half2_rn((v.z - mu) * inv * gv.z + bv.z,
                                       (v.w - mu) * inv * gv.w + bv.w);
        uint2 pk = make_uint2(*(uint32_t*)&h0, *(uint32_t*)&h1);
        *(uint2*)(out16 + (size_t)row * DIM_ + (lane + 32 * i) * 4) = pk;
    }
}

// ================= spiral conv: 3-phase chunked scan =================
__global__ void conv_phase1(const float* __restrict__ x, const float* __restrict__ lng,
                            const float* __restrict__ lnb) {
    int b = blockIdx.x >> 5, c = blockIdx.x & 31, d = threadIdx.x;
    float2 p = g_p[d];
    float gd = lng[d], bd = lnb[d];
    float zr = 0.f, zi = 0.f;
    int row0 = b * L_ + c * CS;
    const float* xp = x + (size_t)row0 * DIM_ + d;
    #pragma unroll 4
    for (int j = 0; j < CS; j++) {
        float2 st = g_stat[row0 + j];
        float hv = (xp[(size_t)j * DIM_] - st.x) * st.y * gd + bd;
        float nr = p.x * zr - p.y * zi + hv;
        zi = p.x * zi + p.y * zr;
        zr = nr;
    }
    g_carry[(b * NC + c) * DIM_ + d] = make_float2(zr, zi);
}

__global__ void conv_phase2() {
    int b = blockIdx.x;
    int d = blockIdx.y * 256 + threadIdx.x;
    float2 pc = g_p64[d];
    float2 cv[NC];
    #pragma unroll
    for (int c = 0; c < NC; c++) cv[c] = g_carry[(b * NC + c) * DIM_ + d];
    float zr = 0.f, zi = 0.f;
    #pragma unroll
    for (int c = 0; c < NC; c++) {
        g_zin[(b * NC + c) * DIM_ + d] = make_float2(zr, zi);
        float nr = pc.x * zr - pc.y * zi + cv[c].x;
        zi = pc.x * zi + pc.y * zr + cv[c].y;
        zr = nr;
    }
}

__global__ void conv_phase3(const float* __restrict__ x, const float* __restrict__ lng,
                            const float* __restrict__ lnb,
                            const float* __restrict__ lre, const float* __restrict__ lim,
                            float* __restrict__ y) {
    int b = blockIdx.x >> 5, c = blockIdx.x & 31, d = threadIdx.x;
    float2 p  = g_p[d];
    float2 pi = g_pinit[d];
    float2 pc = g_p64[d];
    float2 z  = g_zin[(b * NC + c) * DIM_ + d];
    float gd = lng[d], bd = lnb[d];
    float twr = 1.f, twi = 0.f;
    for (int i = 0; i < c; i++) {
        float nr = twr * pc.x - twi * pc.y;
        twi = twr * pc.y + twi * pc.x;
        twr = nr;
    }
    float pwr = twr * p.x - twi * p.y;
    float pwi = twr * p.y + twi * p.x;
    float lr = lre[b * DIM_ + d], li = lim[b * DIM_ + d];
    int row0 = b * L_ + c * CS;
    size_t base = (size_t)row0 * DIM_ + d;
    #pragma unroll 4
    for (int j = 0; j < CS; j++) {
        float xv = x[base + (size_t)j * DIM_];
        float2 st = g_stat[row0 + j];
        float hv = (xv - st.x) * st.y * gd + bd;
        float nr = p.x * z.x - p.y * z.y + hv;
        z.y = p.x * z.y + p.y * z.x;
        z.x = nr;
        float val = pi.x * z.x - pi.y * z.y + lr * pwr - li * pwi;
        y[base + (size_t)j * DIM_] = val + xv;
        float npr = pwr * p.x - pwi * p.y;
        pwi = pwr * p.y + pwi * p.x;
        pwr = npr;
    }
}

// ======== weight transpose + cast ([K,N] fp32 -> [N,K] fp16) ========
__global__ void transpose_h(const float* __restrict__ in, __half* __restrict__ out,
                            int R, int Ccols) {
    __shared__ float t[32][33];
    int bx = blockIdx.x * 32, by = blockIdx.y * 32;
    int tx = threadIdx.x, ty = threadIdx.y;
    #pragma unroll
    for (int j = 0; j < 32; j += 8)
        t[ty + j][tx] = in[(size_t)(by + ty + j) * Ccols + bx + tx];
    __syncthreads();
    #pragma unroll
    for (int j = 0; j < 32; j += 8)
        out[(size_t)(bx + ty + j) * R + by + tx] = __float2half(t[tx][ty + j]);
}

// ======= fp16 tensor-core GEMM (mma.sync m16n8k16 + ldmatrix) =======
// CTA tile 128 x CTN (CTN=256: 1 CTA/SM; CTN=128: 2 CTA/SM), BK=32,
// 8 warps in 2x4 grid, warp tile 64 x (CTN/4), 3-stage ring, 1 barrier/kt.
// EPI==0: act(half) = silu(acc + bias);  EPI==1: out(f32) = acc + bias + res
#define TBK 32
#define ROW_H 72                         // padded stride in halves (144B)

template <int EPI, int CTN>
__global__ __launch_bounds__(256, (CTN == 128) ? 2 : 1) void hgemm(
    const __half* __restrict__ A, const __half* __restrict__ Bt,
    const float* __restrict__ bias, const float* __restrict__ res,
    __half* __restrict__ Ch, float* __restrict__ Cf, int M, int N, int K) {
    constexpr int WNW = CTN / 4;         // warp n-width: 64 or 32
    constexpr int NT  = WNW / 8;         // n-subtiles: 8 or 4
    constexpr int NP  = NT / 2;          // ldmatrix x4 B loads: 4 or 2
    constexpr int BCH = CTN / 64;        // B 16B-chunks per thread: 4 or 2
    constexpr int A_H = 128 * ROW_H;
    constexpr int STG = (128 + CTN) * ROW_H;

    extern __shared__ __half sm[];
    int tid = threadIdx.x, wid = tid >> 5, lane = tid & 31;
    int g = lane >> 2, l4 = lane & 3;
    int wm = (wid & 1) * 64;
    int wn = (wid >> 1) * WNW;
    int bm = blockIdx.y * 128, bn = blockIdx.x * CTN;
    const int NK = K / TBK;

    int mat = lane >> 3, rr = lane & 7;
    uint32_t aoff[4], boff[NP];
    #pragma unroll
    for (int mt = 0; mt < 4; mt++)
        aoff[mt] = (uint32_t)((wm + mt * 16 + (mat & 1) * 8 + rr) * 144 + (mat >> 1) * 16);
    #pragma unroll
    for (int np = 0; np < NP; np++)
        boff[np] = (uint32_t)((wn + np * 16 + (mat >> 1) * 8 + rr) * 144 + (mat & 1) * 16);

    auto load_stage = [&](int s, int k0) {
        uint32_t base = smem_u32(sm + (size_t)s * STG);
        #pragma unroll
        for (int i = 0; i < 2; i++) {
            int c = tid + i * 256;
            int row = c >> 2, kc = c & 3;
            cp_async16(base + row * 144 + kc * 16,
                       A + (size_t)(bm + row) * K + k0 + kc * 8);
        }
        uint32_t bb = base + A_H * 2;
        #pragma unroll
        for (int i = 0; i < BCH; i++) {
            int c = tid + i * 256;
            int row = c >> 2, kc = c & 3;
            cp_async16(bb + row * 144 + kc * 16,
                       Bt + (size_t)(bn + row) * K + k0 + kc * 8);
        }
    };

    float acc[4][NT][4];
    #pragma unroll
    for (int i = 0; i < 4; i++)
        #pragma unroll
        for (int j = 0; j < NT; j++)
            #pragma unroll
            for (int r = 0; r < 4; r++) acc[i][j][r] = 0.f;

    load_stage(0, 0);       CP_COMMIT();
    load_stage(1, TBK);     CP_COMMIT();

    for (int kt = 0; kt < NK; kt++) {
        if (kt + 1 < NK) CP_WAIT(1); else CP_WAIT(0);
        __syncthreads();
        // barrier above guarantees stage (kt-1)%3 == (kt+2)%3 is free
        if (kt + 2 < NK) load_stage((kt + 2) % 3, (kt + 2) * TBK);
        CP_COMMIT();
        uint32_t sa = smem_u32(sm + (size_t)(kt % 3) * STG);
        uint32_t sb = sa + A_H * 2;
        #pragma unroll
        for (int ks = 0; ks < TBK; ks += 16) {
            uint32_t af[4][4], bf[NT][2];
            #pragma unroll
            for (int mt = 0; mt < 4; mt++)
                LDSM_X4(af[mt][0], af[mt][1], af[mt][2], af[mt][3],
                        sa + aoff[mt] + ks * 2);
            #pragma unroll
            for (int np = 0; np < NP; np++)
                LDSM_X4(bf[2 * np][0], bf[2 * np][1], bf[2 * np + 1][0], bf[2 * np + 1][1],
                        sb + boff[np] + ks * 2);
            #pragma unroll
            for (int mt = 0; mt < 4; mt++)
                #pragma unroll
                for (int nt = 0; nt < NT; nt++) {
                    asm volatile(
                        "mma.sync.aligned.m16n8k16.row.col.f32.f16.f16.f32 "
                        "{%0,%1,%2,%3}, {%4,%5,%6,%7}, {%8,%9}, {%0,%1,%2,%3};"
                        : "+f"(acc[mt][nt][0]), "+f"(acc[mt][nt][1]),
                          "+f"(acc[mt][nt][2]), "+f"(acc[mt][nt][3])
                        : "r"(af[mt][0]), "r"(af[mt][1]), "r"(af[mt][2]), "r"(af[mt][3]),
                          "r"(bf[nt][0]), "r"(bf[nt][1]));
                }
        }
    }

    // ---- epilogue ----
    #pragma unroll
    for (int mt = 0; mt < 4; mt++) {
        int r0 = bm + wm + mt * 16 + g;
        #pragma unroll
        for (int nt = 0; nt < NT; nt++) {
            int col = bn + wn + nt * 8 + 2 * l4;
            float bv0 = bias[col], bv1 = bias[col + 1];
            #pragma unroll
            for (int h = 0; h < 2; h++) {
                int row = r0 + h * 8;
                size_t off = (size_t)row * N + col;
                float v0 = acc[mt][nt][2 * h + 0] + bv0;
                float v1 = acc[mt][nt][2 * h + 1] + bv1;
                if (EPI == 0) {
                    v0 = v0 / (1.f + expf(-v0));
                    v1 = v1 / (1.f + expf(-v1));
                    __half2 hv = __floats2half2_rn(v0, v1);
                    *(__half2*)&Ch[off] = hv;
                } else {
                    v0 += res[off];
                    v1 += res[off + 1];
                    *(float2*)&Cf[off] = make_float2(v0, v1);
                }
            }
        }
    }
}

// ================= launch =================
extern "C" void kernel_launch(void* const* d_in, const int* in_sizes, int n_in,
                              void* d_out, int out_size) {
    const float* x      = (const float*)d_in[0];
    const float* ln_g   = (const float*)d_in[1];
    const float* ln_b   = (const float*)d_in[2];
    const float* phazor = (const float*)d_in[3];
    const float* phinit = (const float*)d_in[4];
    const float* w1     = (const float*)d_in[5];
    const float* b1     = (const float*)d_in[6];
    const float* w2     = (const float*)d_in[7];
    const float* b2     = (const float*)d_in[8];
    const float* lre    = (const float*)d_in[9];
    const float* lim    = (const float*)d_in[10];
    float* out = (float*)d_out;

    float *y;
    __half *h2h, *act, *w1h, *w2h;
    cudaGetSymbolAddress((void**)&y,   g_y);
    cudaGetSymbolAddress((void**)&h2h, g_h2h);
    cudaGetSymbolAddress((void**)&act, g_act);
    cudaGetSymbolAddress((void**)&w1h, g_w1h);
    cudaGetSymbolAddress((void**)&w2h, g_w2h);

    const int SMEM1 = 3 * (128 + 256) * ROW_H * 2;   // 165888
    const int SMEM2 = 3 * (128 + 128) * ROW_H * 2;   // 110592
    cudaFuncSetAttribute(hgemm<0,256>, cudaFuncAttributeMaxDynamicSharedMemorySize, SMEM1);
    cudaFuncSetAttribute(hgemm<1,128>, cudaFuncAttributeMaxDynamicSharedMemorySize, SMEM2);

    transpose_h<<<dim3(DFF_ / 32, DIM_ / 32), dim3(32, 8)>>>(w1, w1h, DIM_, DFF_);
    transpose_h<<<dim3(DIM_ / 32, DFF_ / 32), dim3(32, 8)>>>(w2, w2h, DFF_, DIM_);

    phazor_prep<<<1, DIM_>>>(phazor, phinit);
    ln_stats<<<NTOK / 8, 256>>>(x);
    conv_phase1<<<B_ * NC, DIM_>>>(x, ln_g, ln_b);
    conv_phase2<<<dim3(B_, DIM_ / 256), 256>>>();
    conv_phase3<<<B_ * NC, DIM_>>>(x, ln_g, ln_b, lre, lim, y);
    ln2_kernel<<<NTOK / 8, 256>>>(y, ln_g, ln_b, h2h);

    dim3 g1(DFF_ / 256, NTOK / 128);   // 16 x 64
    hgemm<0,256><<<g1, 256, SMEM1>>>(h2h, w1h, b1, nullptr, act, nullptr, NTOK, DFF_, DIM_);
    dim3 g2(DIM_ / 128, NTOK / 128);   // 8 x 64
    hgemm<1,128><<<g2, 256, SMEM2>>>(act, w2h, b2, y, nullptr, out, NTOK, DIM_, DFF_);
}